// round 15
// baseline (speedup 1.0000x reference)
#include <cuda_runtime.h>
#include <cuda_bf16.h>
#include <cstdint>

// ============================================================================
// multimodal_attention via mma.sync (HMMA bf16 hi/lo split) on sm_103
// out[b,q,:] = softmax_k(Q.K^T) @ V       B=32, S=2048, D=64, fp32
//
// R14: wave-tail split-K.  1024 q-tiles / (152 SMs x 3 CTAs = 456 slots)
//      = 2.25 waves -> quantized to 3.  Fix: first 912 tiles (2 full waves)
//      unchanged; last 112 tiles split 3-ways over keys ({11,11,10} KT-tiles),
//      336 tail CTAs fill a short T/3 wave.  Split CTAs atomicAdd
//      un-normalized O + row-sums into scratch; tiny normalize kernel divides.
// ============================================================================

#define BATCH 32
#define SEQ   2048
#define DIM   64
#define QT    64             // q rows per CTA
#define KT    64             // keys per tile
#define NTILES (SEQ / KT)    // 32
#define NTHREADS 128

#define NQTILES  1024        // total q-tiles (32 batch x 16... = SEQ/QT * BATCH)
#define FULLCTAS 912         // q-tiles processed by one CTA (2 full waves of 456)
#define TAILQT   (NQTILES - FULLCTAS)   // 112 split q-tiles
#define GRIDX    (FULLCTAS + TAILQT * 3)  // 1248

#define KV_ELEMS (BATCH * SEQ * DIM)     // 4,194,304

// preconverted K/V scratch (32 MB total); K pre-scaled by log2(e)
__device__ __nv_bfloat16 g_khi[KV_ELEMS];
__device__ __nv_bfloat16 g_klo[KV_ELEMS];
__device__ __nv_bfloat16 g_vhi[KV_ELEMS];
__device__ __nv_bfloat16 g_vlo[KV_ELEMS];

// split-tile accumulators (zeroed in prepass)
__device__ float g_O[TAILQT * QT * DIM];   // un-normalized O partials
__device__ float g_LS[TAILQT * QT];        // row-sum partials

// smem: double buffer, each buf = {KHI,KLO,VHI,VLO} 8KB tiles = 32KB
#define BUF_STRIDE 32768
#define T_KHI 0
#define T_KLO 8192
#define T_VHI 16384
#define T_VLO 24576
#define SMEM_BYTES (2 * BUF_STRIDE)      // 64KB static

__device__ __forceinline__ uint32_t smem_u32(const void* p) {
    uint32_t a;
    asm("{ .reg .u64 t; cvta.to.shared.u64 t, %1; cvt.u32.u64 %0, t; }" : "=r"(a) : "l"(p));
    return a;
}
// 128B rows; xor-swizzle 16B chunks by row&7 -> conflict-free ldmatrix
__device__ __forceinline__ uint32_t swa(int row, int col16) {
    return (uint32_t)(row * 128 + ((col16 ^ (row & 7)) << 4));
}
__device__ __forceinline__ uint32_t packhi(float a, float b) {
    __nv_bfloat162 t = __floats2bfloat162_rn(a, b);
    return *reinterpret_cast<uint32_t*>(&t);
}
__device__ __forceinline__ uint32_t packlo(float a, float b) {
    float ah = __bfloat162float(__float2bfloat16_rn(a));
    float bh = __bfloat162float(__float2bfloat16_rn(b));
    __nv_bfloat162 t = __floats2bfloat162_rn(a - ah, b - bh);
    return *reinterpret_cast<uint32_t*>(&t);
}
__device__ __forceinline__ float ex2f(float x) {
    float r;
    asm("ex2.approx.ftz.f32 %0, %1;" : "=f"(r) : "f"(x));
    return r;
}

#define CP_ASYNC16(SM, GM) \
    asm volatile("cp.async.cg.shared.global [%0], [%1], 16;" :: "r"(SM), "l"(GM) : "memory")
#define CP_COMMIT()  asm volatile("cp.async.commit_group;" ::: "memory")
#define CP_WAIT0()   asm volatile("cp.async.wait_group 0;" ::: "memory")
#define CP_WAIT1()   asm volatile("cp.async.wait_group 1;" ::: "memory")

#define LDSM_X4(R0,R1,R2,R3,ADDR) \
    asm volatile("ldmatrix.sync.aligned.m8n8.x4.shared.b16 {%0,%1,%2,%3}, [%4];" \
                 : "=r"(R0),"=r"(R1),"=r"(R2),"=r"(R3) : "r"(ADDR))
#define LDSM_X4T(R0,R1,R2,R3,ADDR) \
    asm volatile("ldmatrix.sync.aligned.m8n8.x4.trans.shared.b16 {%0,%1,%2,%3}, [%4];" \
                 : "=r"(R0),"=r"(R1),"=r"(R2),"=r"(R3) : "r"(ADDR))
// D += A * B   (m16n8k16, bf16 in, f32 accum)
#define MMA(D,A,B0,B1) \
    asm volatile("mma.sync.aligned.m16n8k16.row.col.f32.bf16.bf16.f32 " \
                 "{%0,%1,%2,%3},{%4,%5,%6,%7},{%8,%9},{%0,%1,%2,%3};" \
                 : "+f"((D)[0]),"+f"((D)[1]),"+f"((D)[2]),"+f"((D)[3]) \
                 : "r"((A)[0]),"r"((A)[1]),"r"((A)[2]),"r"((A)[3]),"r"(B0),"r"(B1))

// ---------------------------------------------------------------------------
// Pre-pass: K,V fp32 -> bf16 hi/lo scratch (K scaled by log2e) + zero the
// split-tile accumulators.
// ---------------------------------------------------------------------------
__global__ __launch_bounds__(256)
void kv_convert_kernel(const float* __restrict__ k, const float* __restrict__ v)
{
    const float LOG2E = 1.4426950408889634f;
    int i = blockIdx.x * 256 + threadIdx.x;          // float4 index
    // zero split accumulators (region is much smaller than the thread count)
    if (i < TAILQT * QT * DIM) g_O[i] = 0.0f;
    if (i < TAILQT * QT)       g_LS[i] = 0.0f;

    float4 kx = reinterpret_cast<const float4*>(k)[i];
    kx.x *= LOG2E; kx.y *= LOG2E; kx.z *= LOG2E; kx.w *= LOG2E;
    float4 vx = reinterpret_cast<const float4*>(v)[i];
    reinterpret_cast<uint2*>(g_khi)[i] = make_uint2(packhi(kx.x, kx.y), packhi(kx.z, kx.w));
    reinterpret_cast<uint2*>(g_klo)[i] = make_uint2(packlo(kx.x, kx.y), packlo(kx.z, kx.w));
    reinterpret_cast<uint2*>(g_vhi)[i] = make_uint2(packhi(vx.x, vx.y), packhi(vx.z, vx.w));
    reinterpret_cast<uint2*>(g_vlo)[i] = make_uint2(packlo(vx.x, vx.y), packlo(vx.z, vx.w));
}

// ---------------------------------------------------------------------------
// Normalize kernel for the split region: out = g_O / g_LS
// ---------------------------------------------------------------------------
__global__ __launch_bounds__(256)
void norm_kernel(float* __restrict__ out)
{
    int e = blockIdx.x * 256 + threadIdx.x;      // float4 index over region
    int row = e >> 4;                            // region row  [0, TAILQT*QT)
    int c4  = e & 15;
    int tix = row >> 6;                          // split tile index
    int r   = row & 63;
    int id  = FULLCTAS + tix;                    // global q-tile id
    int b   = id >> 5, qx = id & 31;
    float inv = 1.0f / g_LS[row];
    float4 o = reinterpret_cast<const float4*>(g_O)[e];
    float4 res = make_float4(o.x * inv, o.y * inv, o.z * inv, o.w * inv);
    reinterpret_cast<float4*>(out + ((size_t)b * SEQ + qx * QT + r) * DIM)[c4] = res;
}

// ---------------------------------------------------------------------------
// Attention kernel
// ---------------------------------------------------------------------------
__global__ __launch_bounds__(NTHREADS, 3)
void attn_mma_kernel(const float* __restrict__ q,
                     float* __restrict__ out)
{
    __shared__ __align__(1024) char smem[SMEM_BYTES];
    const uint32_t sb = smem_u32(smem);
    const int tid  = threadIdx.x;
    const int w    = tid >> 5;                // warp 0..3
    const int lane = tid & 31;

    // ---- decode work unit: full q-tile or 1/3 key-split of a tail q-tile --
    const int bid = blockIdx.x;
    int id, kt0, ktn;
    if (bid < FULLCTAS) {
        id = bid; kt0 = 0; ktn = NTILES;
    } else {
        int x = bid - FULLCTAS;
        int d3 = x / 3;
        int s  = x - d3 * 3;
        id  = FULLCTAS + d3;
        kt0 = s * 11;
        ktn = (s == 2) ? 10 : 11;
    }
    const int ktend = kt0 + ktn;
    const int b     = id >> 5;
    const int qbase = (id & 31) * QT;
    const int wr0   = w * 16;                 // this warp's q-row base in tile

    const size_t kvbase = (size_t)b * SEQ * DIM;   // element offset of this batch

    const __nv_bfloat16* g_arr[4] = { g_khi, g_klo, g_vhi, g_vlo };

    // ---- kick off DMA of tile kt0 into buf0 ----
    {
        const size_t toff = kvbase + (size_t)kt0 * KT * DIM;
#pragma unroll
        for (int i = 0; i < 16; i++) {
            int arr = i >> 2, rc = (i & 3) * NTHREADS + tid;
            int row = rc >> 3, c16 = rc & 7;
            const char* src = (const char*)(g_arr[arr] + toff + row * DIM) + c16 * 16;
            CP_ASYNC16(sb + arr * 8192 + swa(row, c16), src);
        }
        CP_COMMIT();
    }

    // ---- Prologue: stage Q (64x64 f32 -> bf16 hi/lo) into buf1 region ----
    {
        const float* qp = q + ((size_t)b * SEQ + qbase) * DIM;
#pragma unroll
        for (int i = 0; i < (QT * DIM / 4) / NTHREADS; i++) {   // 8 iters
            int idx = i * NTHREADS + tid;
            int row = idx >> 4, f4 = idx & 15;
            float4 x = reinterpret_cast<const float4*>(qp + row * DIM)[f4];
            uint32_t off = swa(row, f4 >> 1) + (f4 & 1) * 8;
            *reinterpret_cast<uint2*>(smem + BUF_STRIDE + off) =
                make_uint2(packhi(x.x, x.y), packhi(x.z, x.w));
            *reinterpret_cast<uint2*>(smem + BUF_STRIDE + 8192 + off) =
                make_uint2(packlo(x.x, x.y), packlo(x.z, x.w));
        }
    }
    __syncthreads();

    // Q fragments (A of m16n8k16): 4 k-chunks of 16, hi and lo
    uint32_t qh[4][4], ql[4][4];
    {
        int arow = wr0 + (lane & 7) + ((lane >> 3) & 1) * 8;
#pragma unroll
        for (int kc = 0; kc < 4; kc++) {
            uint32_t off = swa(arow, kc * 2 + (lane >> 4));
            LDSM_X4(qh[kc][0], qh[kc][1], qh[kc][2], qh[kc][3], sb + BUF_STRIDE + off);
            LDSM_X4(ql[kc][0], ql[kc][1], ql[kc][2], ql[kc][3], sb + BUF_STRIDE + 8192 + off);
        }
    }
    __syncthreads();   // buf1 free for next-tile prefetch after this

    float oacc[8][4];
#pragma unroll
    for (int nt = 0; nt < 8; nt++)
#pragma unroll
        for (int i = 0; i < 4; i++) oacc[nt][i] = 0.0f;
    // row-sum accumulator fed by ones-MMA: every column holds the FULL row sum
    float lsacc[4] = {0.0f, 0.0f, 0.0f, 0.0f};
    const uint32_t ONES = 0x3F803F80u;   // bf16x2 {1.0, 1.0}

    // lane mapping for x4 B-operand ldmatrix
    const int m8 = lane >> 3;     // which 8x8 matrix this lane addresses
    const int r8 = lane & 7;

    for (int t = kt0; t < ktend; t++) {
        const uint32_t bufb = sb + (uint32_t)((t - kt0) & 1) * BUF_STRIDE;

        // ---- prefetch tile t+1 into the other buffer; wait for tile t ----
        if (t + 1 < ktend) {
            const size_t toff = kvbase + (size_t)(t + 1) * KT * DIM;
            const uint32_t nb = sb + (uint32_t)((t + 1 - kt0) & 1) * BUF_STRIDE;
#pragma unroll
            for (int i = 0; i < 16; i++) {
                int arr = i >> 2, rc = (i & 3) * NTHREADS + tid;
                int row = rc >> 3, c16 = rc & 7;
                const char* src = (const char*)(g_arr[arr] + toff + row * DIM) + c16 * 16;
                CP_ASYNC16(nb + arr * 8192 + swa(row, c16), src);
            }
            CP_COMMIT();
            CP_WAIT1();          // oldest group (tile t) complete
        } else {
            CP_WAIT0();
        }
        __syncthreads();

        // ---- MMA1: S[16,64] = Qhi.Khi^T + Qhi.Klo^T + Qlo.Khi^T ----
        float sacc[8][4];
#pragma unroll
        for (int nt = 0; nt < 8; nt++)
#pragma unroll
            for (int i = 0; i < 4; i++) sacc[nt][i] = 0.0f;

#pragma unroll
        for (int half = 0; half < 2; half++) {
#pragma unroll
            for (int kc = 0; kc < 4; kc++) {
#pragma unroll
                for (int ntl = 0; ntl < 2; ntl++) {
                    int ntp = half * 2 + ntl;
                    int krow  = (ntp * 2 + (m8 >> 1)) * 8 + r8;
                    uint32_t off = swa(krow, kc * 2 + (m8 & 1));
                    uint32_t bh0, bh1, bh2, bh3, bl0, bl1, bl2, bl3;
                    LDSM_X4(bh0, bh1, bh2, bh3, bufb + T_KHI + off);
                    LDSM_X4(bl0, bl1, bl2, bl3, bufb + T_KLO + off);
                    MMA(sacc[2*ntp],   qh[kc], bh0, bh1);
                    MMA(sacc[2*ntp+1], qh[kc], bh2, bh3);
                    MMA(sacc[2*ntp],   qh[kc], bl0, bl1);
                    MMA(sacc[2*ntp+1], qh[kc], bl2, bl3);
                    MMA(sacc[2*ntp],   ql[kc], bh0, bh1);
                    MMA(sacc[2*ntp+1], ql[kc], bh2, bh3);
                }
            }
        }

        // ---- per key-half: exp(S) -> rn Phi fragments, ones-MMA sum, MMA2 --
#pragma unroll
        for (int half = 0; half < 2; half++) {
            uint32_t ph[2][4];
#pragma unroll
            for (int ntl = 0; ntl < 4; ntl++) {
                int nt = half * 4 + ntl;
                float p0 = ex2f(sacc[nt][0]);
                float p1 = ex2f(sacc[nt][1]);
                float p2 = ex2f(sacc[nt][2]);
                float p3 = ex2f(sacc[nt][3]);
                int kcl = ntl >> 1, h = (ntl & 1) * 2;
                ph[kcl][h]     = packhi(p0, p1);
                ph[kcl][h + 1] = packhi(p2, p3);
            }
#pragma unroll
            for (int kcl = 0; kcl < 2; kcl++) {
                int kcg = half * 2 + kcl;
                MMA(lsacc, ph[kcl], ONES, ONES);
#pragma unroll
                for (int ntp = 0; ntp < 4; ntp++) {
                    int vrow = kcg * 16 + (m8 & 1) * 8 + r8;
                    uint32_t off = swa(vrow, ntp * 2 + (m8 >> 1));
                    uint32_t bh0, bh1, bh2, bh3, bl0, bl1, bl2, bl3;
                    LDSM_X4T(bh0, bh1, bh2, bh3, bufb + T_VHI + off);
                    LDSM_X4T(bl0, bl1, bl2, bl3, bufb + T_VLO + off);
                    MMA(oacc[2*ntp],   ph[kcl], bh0, bh1);
                    MMA(oacc[2*ntp+1], ph[kcl], bh2, bh3);
                    MMA(oacc[2*ntp],   ph[kcl], bl0, bl1);
                    MMA(oacc[2*ntp+1], ph[kcl], bl2, bl3);
                }
            }
        }
        __syncthreads();   // tile t reads done -> buffer reusable next iter
    }

    const int r = lane >> 2, c = lane & 3;

    if (bid < FULLCTAS) {
        // ---- full tile: normalize + store (row sums complete per-lane) ----
        const float inv0 = 1.0f / lsacc[0];
        const float inv1 = 1.0f / lsacc[2];
        float* op0 = out + ((size_t)b * SEQ + qbase + wr0 + r) * DIM;
        float* op1 = op0 + 8 * DIM;
#pragma unroll
        for (int nt = 0; nt < 8; nt++) {
            float2 t0 = make_float2(oacc[nt][0] * inv0, oacc[nt][1] * inv0);
            float2 t1 = make_float2(oacc[nt][2] * inv1, oacc[nt][3] * inv1);
            *reinterpret_cast<float2*>(op0 + nt * 8 + 2 * c) = t0;
            *reinterpret_cast<float2*>(op1 + nt * 8 + 2 * c) = t1;
        }
    } else {
        // ---- split tile: accumulate un-normalized partials ----
        const int tix = id - FULLCTAS;
        float* gO0 = g_O + ((size_t)(tix * QT + wr0 + r)) * DIM;
        float* gO1 = gO0 + 8 * DIM;
#pragma unroll
        for (int nt = 0; nt < 8; nt++) {
            atomicAdd(&gO0[nt * 8 + 2 * c],     oacc[nt][0]);
            atomicAdd(&gO0[nt * 8 + 2 * c + 1], oacc[nt][1]);
            atomicAdd(&gO1[nt * 8 + 2 * c],     oacc[nt][2]);
            atomicAdd(&gO1[nt * 8 + 2 * c + 1], oacc[nt][3]);
        }
        if (c == 0) {
            atomicAdd(&g_LS[tix * QT + wr0 + r],     lsacc[0]);
            atomicAdd(&g_LS[tix * QT + wr0 + 8 + r], lsacc[2]);
        }
    }
}

extern "C" void kernel_launch(void* const* d_in, const int* in_sizes, int n_in,
                              void* d_out, int out_size)
{
    const float* q = (const float*)d_in[0];
    const float* k = (const float*)d_in[1];
    const float* v = (const float*)d_in[2];
    float* out = (float*)d_out;

    kv_convert_kernel<<<KV_ELEMS / 4 / 256, 256>>>(k, v);

    attn_mma_kernel<<<GRIDX, NTHREADS>>>(q, out);

    norm_kernel<<<(TAILQT * QT * DIM / 4) / 256, 256>>>(out);
}